// round 2
// baseline (speedup 1.0000x reference)
#include <cuda_runtime.h>
#include <math.h>

#define NROWS 8192
#define DIM   128
#define HID1  512
#define HID2  256
#define NUSERS 512

// ---------------- scratch (device globals; no allocations allowed) ----------------
__device__ float g_hist[NROWS * DIM];
__device__ float g_h1[NROWS * HID1];
__device__ float g_h2[NROWS * HID2];
__device__ int   g_cnt[NUSERS];
__device__ int   g_off[NUSERS];
__device__ int   g_fill[NUSERS];
__device__ int   g_idx[NROWS];
__device__ int   g_tsb[NROWS];
__device__ int   g_rowcnt[NROWS];
__device__ int   g_is64;       // user/timestamp stored as int64?
__device__ int   g_clickbyte;  // is_click stored as 1-byte bool?

// ---------------- dtype detection (deterministic, data-driven) ----------------
__global__ void k_detect(const void* ts, const void* click) {
    __shared__ int s_ts_or, s_click_big;
    if (threadIdx.x == 0) { s_ts_or = 0; s_click_big = 0; }
    __syncthreads();
    // If timestamps are int64 (values < 2^31), every odd 32-bit word is 0.
    const unsigned int* tsw = (const unsigned int*)ts;
    unsigned int acc = 0;
    for (int i = threadIdx.x; i < 2048; i += 256) acc |= tsw[2 * i + 1];
    if (acc) atomicOr(&s_ts_or, 1);
    // If click is 1-byte bool, some 32-bit word of the first 8192 bytes is >1.
    const unsigned int* cw = (const unsigned int*)click;
    int big = 0;
    for (int i = threadIdx.x; i < 2048; i += 256)
        if (cw[i] > 1u) big = 1;
    if (big) atomicOr(&s_click_big, 1);
    __syncthreads();
    if (threadIdx.x == 0) {
        g_is64 = (s_ts_or == 0) ? 1 : 0;
        g_clickbyte = s_click_big ? 1 : 0;
    }
}

__device__ __forceinline__ int ld_user(const void* p, int j, int is64) {
    return is64 ? (int)((const long long*)p)[j] : ((const int*)p)[j];
}
__device__ __forceinline__ long long ld_ts(const void* p, int j, int is64) {
    return is64 ? ((const long long*)p)[j] : (long long)((const int*)p)[j];
}
__device__ __forceinline__ int ld_click(const void* p, int j, int cb) {
    return cb ? (((const unsigned char*)p)[j] != 0) : (((const int*)p)[j] != 0);
}

// ---------------- bucketing ----------------
__global__ void k_zero() {
    int t = threadIdx.x;
    if (t < NUSERS) { g_cnt[t] = 0; g_fill[t] = 0; }
}

__global__ void k_count(const void* __restrict__ user, const void* __restrict__ click) {
    int j = blockIdx.x * blockDim.x + threadIdx.x;
    if (j >= NROWS) return;
    int is64 = g_is64, cb = g_clickbyte;
    if (ld_click(click, j, cb)) atomicAdd(&g_cnt[ld_user(user, j, is64)], 1);
}

__global__ void k_scan() {  // 1 block, 512 threads: exclusive prefix over g_cnt
    __shared__ int s[NUSERS];
    int t = threadIdx.x;
    int v = g_cnt[t];
    s[t] = v;
    __syncthreads();
    for (int off = 1; off < NUSERS; off <<= 1) {
        int x = (t >= off) ? s[t - off] : 0;
        __syncthreads();
        s[t] += x;
        __syncthreads();
    }
    g_off[t] = s[t] - v;
}

__global__ void k_scatter(const void* __restrict__ user, const void* __restrict__ ts,
                          const void* __restrict__ click) {
    int j = blockIdx.x * blockDim.x + threadIdx.x;
    if (j >= NROWS) return;
    int is64 = g_is64, cb = g_clickbyte;
    if (ld_click(click, j, cb)) {
        int u = ld_user(user, j, is64);
        int p = atomicAdd(&g_fill[u], 1);
        int pos = g_off[u] + p;
        g_idx[pos] = j;
        g_tsb[pos] = (int)ld_ts(ts, j, is64);
    }
}

// deterministic order within each bucket (atomic scatter order is arbitrary)
__global__ void k_sort() {
    if (threadIdx.x != 0) return;
    int u = blockIdx.x;
    int b = g_off[u], n = g_cnt[u];
    for (int i = 1; i < n; i++) {
        int kj = g_idx[b + i], kt = g_tsb[b + i];
        int p = i - 1;
        while (p >= 0 && g_idx[b + p] > kj) {
            g_idx[b + p + 1] = g_idx[b + p];
            g_tsb[b + p + 1] = g_tsb[b + p];
            p--;
        }
        g_idx[b + p + 1] = kj;
        g_tsb[b + p + 1] = kt;
    }
}

// ---------------- history aggregation: one block (128 thr) per row ----------------
__global__ void k_hist(const float* __restrict__ ad, const void* __restrict__ user,
                       const void* __restrict__ ts) {
    int i = blockIdx.x;
    int t = threadIdx.x;   // 0..127 = embedding dim
    int is64 = g_is64;
    int u = ld_user(user, i, is64);
    long long ti = ld_ts(ts, i, is64);
    int b = g_off[u], n = g_cnt[u];
    float acc = 0.f;
    int c = 0;
    for (int k = 0; k < n; k++) {
        long long tj = (long long)g_tsb[b + k];
        if (tj < ti) {            // reference: timestamp[i] > timestamp[j]
            int j = g_idx[b + k];
            acc += ad[j * DIM + t];
            c++;
        }
    }
    g_hist[i * DIM + t] = c ? acc / (float)c : 0.f;
    if (t == 0) g_rowcnt[i] = c;
}

// ---------------- tiled SGEMM, SiLU epilogue ----------------
// C[M,Nn] = silu(A[M,K] @ W[K,Nn] + bias)
template<int BM, int BN, int BK, int TM, int TN>
__global__ __launch_bounds__(256)
void gemm_silu(const float* __restrict__ A, const float* __restrict__ W,
               const float* __restrict__ bias, float* __restrict__ C,
               int M, int K, int Nn) {
    __shared__ float As[BK][BM];
    __shared__ float Bs[BK][BN];
    const int tid = threadIdx.x;
    const int tx = tid % (BN / TN);
    const int ty = tid / (BN / TN);
    const int bm = blockIdx.y * BM;
    const int bn = blockIdx.x * BN;

    float acc[TM][TN];
    #pragma unroll
    for (int m = 0; m < TM; m++)
        #pragma unroll
        for (int n = 0; n < TN; n++) acc[m][n] = 0.f;

    for (int k0 = 0; k0 < K; k0 += BK) {
        #pragma unroll
        for (int i = tid; i < BM * BK / 4; i += 256) {
            int idx = i * 4;
            int r = idx / BK, c = idx % BK;
            float4 v = *(const float4*)&A[(size_t)(bm + r) * K + k0 + c];
            As[c + 0][r] = v.x; As[c + 1][r] = v.y; As[c + 2][r] = v.z; As[c + 3][r] = v.w;
        }
        #pragma unroll
        for (int i = tid; i < BK * BN / 4; i += 256) {
            int idx = i * 4;
            int r = idx / BN, c = idx % BN;
            *(float4*)&Bs[r][c] = *(const float4*)&W[(size_t)(k0 + r) * Nn + bn + c];
        }
        __syncthreads();
        #pragma unroll
        for (int k = 0; k < BK; k++) {
            float a[TM], b[TN];
            #pragma unroll
            for (int m = 0; m < TM; m++) a[m] = As[k][ty * TM + m];
            #pragma unroll
            for (int n = 0; n < TN; n++) b[n] = Bs[k][tx * TN + n];
            #pragma unroll
            for (int m = 0; m < TM; m++)
                #pragma unroll
                for (int n = 0; n < TN; n++) acc[m][n] += a[m] * b[n];
        }
        __syncthreads();
    }

    #pragma unroll
    for (int m = 0; m < TM; m++) {
        int row = bm + ty * TM + m;
        #pragma unroll
        for (int n = 0; n < TN; n++) {
            int col = bn + tx * TN + n;
            float x = acc[m][n] + bias[col];
            float s = x / (1.f + __expf(-x));
            C[(size_t)row * Nn + col] = s;
        }
    }
}

// ---------------- final GEMM: bias + double-L2-normalize + empty-mask ----------------
// BN == Nn == 128 so each block owns complete rows.
template<int BM, int BK, int TM, int TN>
__global__ __launch_bounds__(256)
void gemm_norm(const float* __restrict__ A, const float* __restrict__ W,
               const float* __restrict__ bias, const int* __restrict__ rowcnt,
               float* __restrict__ C, int M, int K) {
    const int BN = 128;
    __shared__ float As[BK][BM];
    __shared__ float Bs[BK][BN];
    __shared__ float scale_sh[BM];
    const int tid = threadIdx.x;
    const int tx = tid % (BN / TN);   // 16 col-groups
    const int ty = tid / (BN / TN);   // BM/TM row-groups
    const int bm = blockIdx.y * BM;

    float acc[TM][TN];
    #pragma unroll
    for (int m = 0; m < TM; m++)
        #pragma unroll
        for (int n = 0; n < TN; n++) acc[m][n] = 0.f;

    for (int k0 = 0; k0 < K; k0 += BK) {
        #pragma unroll
        for (int i = tid; i < BM * BK / 4; i += 256) {
            int idx = i * 4;
            int r = idx / BK, c = idx % BK;
            float4 v = *(const float4*)&A[(size_t)(bm + r) * K + k0 + c];
            As[c + 0][r] = v.x; As[c + 1][r] = v.y; As[c + 2][r] = v.z; As[c + 3][r] = v.w;
        }
        #pragma unroll
        for (int i = tid; i < BK * BN / 4; i += 256) {
            int idx = i * 4;
            int r = idx / BN, c = idx % BN;
            *(float4*)&Bs[r][c] = *(const float4*)&W[(size_t)(k0 + r) * BN + c];
        }
        __syncthreads();
        #pragma unroll
        for (int k = 0; k < BK; k++) {
            float a[TM], b[TN];
            #pragma unroll
            for (int m = 0; m < TM; m++) a[m] = As[k][ty * TM + m];
            #pragma unroll
            for (int n = 0; n < TN; n++) b[n] = Bs[k][tx * TN + n];
            #pragma unroll
            for (int m = 0; m < TM; m++)
                #pragma unroll
                for (int n = 0; n < TN; n++) acc[m][n] += a[m] * b[n];
        }
        __syncthreads();
    }

    // bias + row sq-sums
    float x[TM][TN];
    float sq[TM];
    #pragma unroll
    for (int m = 0; m < TM; m++) {
        sq[m] = 0.f;
        #pragma unroll
        for (int n = 0; n < TN; n++) {
            float v = acc[m][n] + bias[tx * TN + n];
            x[m][n] = v;
            sq[m] += v * v;
        }
    }
    // reduce across the 16 lanes sharing a row-group (width=16 keeps ty-groups separate)
    #pragma unroll
    for (int off = 8; off > 0; off >>= 1)
        #pragma unroll
        for (int m = 0; m < TM; m++)
            sq[m] += __shfl_down_sync(0xffffffffu, sq[m], off, 16);

    if (tx == 0) {
        #pragma unroll
        for (int m = 0; m < TM; m++) {
            int row = bm + ty * TM + m;
            float s = sq[m];
            float sc = 0.f;
            if (rowcnt[row] > 0 && s > 0.f) sc = 1.0f / sqrtf(s);
            scale_sh[ty * TM + m] = sc;
        }
    }
    __syncthreads();

    #pragma unroll
    for (int m = 0; m < TM; m++) {
        int row = bm + ty * TM + m;
        float sc = scale_sh[ty * TM + m];
        #pragma unroll
        for (int n = 0; n < TN; n++) {
            C[(size_t)row * BN + tx * TN + n] = x[m][n] * sc;
        }
    }
}

// ---------------- launch ----------------
extern "C" void kernel_launch(void* const* d_in, const int* in_sizes, int n_in,
                              void* d_out, int out_size) {
    const float* ad    = (const float*)d_in[0];
    const void*  user  = d_in[1];
    const void*  ts    = d_in[2];
    const void*  click = d_in[3];
    const float* W1 = (const float*)d_in[4];
    const float* b1 = (const float*)d_in[5];
    const float* W2 = (const float*)d_in[6];
    const float* b2 = (const float*)d_in[7];
    const float* W3 = (const float*)d_in[8];
    const float* b3 = (const float*)d_in[9];
    float* out = (float*)d_out;

    float *hist, *h1, *h2;
    int *rowcnt;
    cudaGetSymbolAddress((void**)&hist,   g_hist);
    cudaGetSymbolAddress((void**)&h1,     g_h1);
    cudaGetSymbolAddress((void**)&h2,     g_h2);
    cudaGetSymbolAddress((void**)&rowcnt, g_rowcnt);

    k_detect<<<1, 256>>>(ts, click);
    k_zero<<<1, NUSERS>>>();
    k_count<<<(NROWS + 255) / 256, 256>>>(user, click);
    k_scan<<<1, NUSERS>>>();
    k_scatter<<<(NROWS + 255) / 256, 256>>>(user, ts, click);
    k_sort<<<NUSERS, 32>>>();
    k_hist<<<NROWS, DIM>>>(ad, user, ts);

    // L1: [8192,128] @ [128,512] -> silu -> h1
    gemm_silu<128, 128, 16, 8, 8><<<dim3(HID1 / 128, NROWS / 128), 256>>>(
        hist, W1, b1, h1, NROWS, DIM, HID1);
    // L2: [8192,512] @ [512,256] -> silu -> h2
    gemm_silu<128, 128, 16, 8, 8><<<dim3(HID2 / 128, NROWS / 128), 256>>>(
        h1, W2, b2, h2, NROWS, HID1, HID2);
    // L3: [8192,256] @ [256,128] + bias -> L2 norm -> mask empty -> out
    gemm_norm<64, 16, 4, 8><<<dim3(1, NROWS / 64), 256>>>(
        h2, W3, b3, rowcnt, out, NROWS, HID2);
}

// round 4
// speedup vs baseline: 1.8378x; 1.8378x over previous
#include <cuda_runtime.h>
#include <cuda_bf16.h>
#include <cstdint>
#include <math.h>

#define NROWS 8192
#define DIM   128
#define HID1  512
#define HID2  256
#define NUSERS 512

// ============================ scratch ============================
__device__ __align__(256) __nv_bfloat16 g_a0hi[NROWS * DIM],  g_a0lo[NROWS * DIM];
__device__ __align__(256) __nv_bfloat16 g_a1hi[NROWS * HID1], g_a1lo[NROWS * HID1];
__device__ __align__(256) __nv_bfloat16 g_a2hi[NROWS * HID2], g_a2lo[NROWS * HID2];
__device__ __align__(256) __nv_bfloat16 g_w1hi[HID1 * DIM],   g_w1lo[HID1 * DIM];   // [N,K]
__device__ __align__(256) __nv_bfloat16 g_w2hi[HID2 * HID1],  g_w2lo[HID2 * HID1];
__device__ __align__(256) __nv_bfloat16 g_w3hi[DIM * HID2],   g_w3lo[DIM * HID2];
__device__ int g_cnt[NUSERS], g_off[NUSERS];
__device__ int g_idx[NROWS], g_tsb[NROWS];
__device__ int g_rowcnt[NROWS];
__device__ int g_is64, g_clickbyte;

// ============================ small helpers ============================
__device__ __forceinline__ uint32_t smem_to_u32(const void* p) {
    uint32_t a;
    asm("{ .reg .u64 t; cvta.to.shared.u64 t, %1; cvt.u32.u64 %0, t; }" : "=r"(a) : "l"(p));
    return a;
}
__device__ __forceinline__ void cp_async16(uint32_t smem, const void* gmem) {
    asm volatile("cp.async.cg.shared.global [%0], [%1], 16;" :: "r"(smem), "l"(gmem));
}
#define CP_COMMIT() asm volatile("cp.async.commit_group;" ::: "memory")
#define CP_WAIT(n)  asm volatile("cp.async.wait_group %0;" :: "n"(n) : "memory")

__device__ __forceinline__ void mma_bf16(float d[4], const uint32_t a[4], const uint32_t b[2]) {
    asm volatile(
        "mma.sync.aligned.m16n8k16.row.col.f32.bf16.bf16.f32 "
        "{%0,%1,%2,%3}, {%4,%5,%6,%7}, {%8,%9}, {%0,%1,%2,%3};"
        : "+f"(d[0]), "+f"(d[1]), "+f"(d[2]), "+f"(d[3])
        : "r"(a[0]), "r"(a[1]), "r"(a[2]), "r"(a[3]), "r"(b[0]), "r"(b[1]));
}

__device__ __forceinline__ int ld_user(const void* p, int j, int is64) {
    return is64 ? (int)((const long long*)p)[j] : ((const int*)p)[j];
}
__device__ __forceinline__ long long ld_ts(const void* p, int j, int is64) {
    return is64 ? ((const long long*)p)[j] : (long long)((const int*)p)[j];
}
__device__ __forceinline__ int ld_click(const void* p, int j, int cb) {
    return cb ? (((const unsigned char*)p)[j] != 0) : (((const int*)p)[j] != 0);
}

// ============ fused prep: detect + count + scan + scatter + sort (1 block) ============
__global__ void k_prep(const void* __restrict__ user, const void* __restrict__ ts,
                       const void* __restrict__ click) {
    __shared__ int cnt[NUSERS], off[NUSERS], fill[NUSERS];
    __shared__ int s_ts_or, s_click_big;
    int t = threadIdx.x;   // 0..511
    if (t == 0) { s_ts_or = 0; s_click_big = 0; }
    __syncthreads();
    {
        const unsigned int* tsw = (const unsigned int*)ts;
        unsigned int acc = 0;
        for (int i = t; i < 2048; i += NUSERS) acc |= tsw[2 * i + 1];
        if (acc) atomicOr(&s_ts_or, 1);
        const unsigned int* cw = (const unsigned int*)click;
        int big = 0;
        for (int i = t; i < 2048; i += NUSERS) if (cw[i] > 1u) big = 1;
        if (big) atomicOr(&s_click_big, 1);
    }
    cnt[t] = 0; fill[t] = 0;
    __syncthreads();
    int is64 = (s_ts_or == 0) ? 1 : 0;
    int cb = s_click_big ? 1 : 0;
    for (int j = t; j < NROWS; j += NUSERS)
        if (ld_click(click, j, cb)) atomicAdd(&cnt[ld_user(user, j, is64)], 1);
    __syncthreads();
    {
        int v = cnt[t];
        off[t] = v;
        __syncthreads();
        for (int o = 1; o < NUSERS; o <<= 1) {
            int x = (t >= o) ? off[t - o] : 0;
            __syncthreads();
            off[t] += x;
            __syncthreads();
        }
        off[t] -= v;
    }
    __syncthreads();
    for (int j = t; j < NROWS; j += NUSERS)
        if (ld_click(click, j, cb)) {
            int u = ld_user(user, j, is64);
            int pos = off[u] + atomicAdd(&fill[u], 1);
            g_idx[pos] = j;
            g_tsb[pos] = (int)ld_ts(ts, j, is64);
        }
    __syncthreads();
    {
        int b = off[t], n = cnt[t];
        for (int i = 1; i < n; i++) {
            int kj = g_idx[b + i], kt = g_tsb[b + i];
            int p = i - 1;
            while (p >= 0 && g_idx[b + p] > kj) {
                g_idx[b + p + 1] = g_idx[b + p];
                g_tsb[b + p + 1] = g_tsb[b + p];
                p--;
            }
            g_idx[b + p + 1] = kj;
            g_tsb[b + p + 1] = kt;
        }
    }
    g_off[t] = off[t];
    g_cnt[t] = cnt[t];
    if (t == 0) { g_is64 = is64; g_clickbyte = cb; }
}

// ============ history: mean of clicked-earlier ad rows -> bf16 hi/lo ============
__global__ void k_hist(const float* __restrict__ ad, const void* __restrict__ user,
                       const void* __restrict__ ts) {
    int i = blockIdx.x;
    int t = threadIdx.x;
    int is64 = g_is64;
    int u = ld_user(user, i, is64);
    long long ti = ld_ts(ts, i, is64);
    int b = g_off[u], n = g_cnt[u];
    float acc = 0.f;
    int c = 0;
    for (int k = 0; k < n; k++) {
        if ((long long)g_tsb[b + k] < ti) {
            acc += ad[g_idx[b + k] * DIM + t];
            c++;
        }
    }
    float v = c ? acc / (float)c : 0.f;
    __nv_bfloat16 hi = __float2bfloat16(v);
    __nv_bfloat16 lo = __float2bfloat16(v - __bfloat162float(hi));
    g_a0hi[i * DIM + t] = hi;
    g_a0lo[i * DIM + t] = lo;
    if (t == 0) g_rowcnt[i] = c;
}

// ============ weight transpose + hi/lo split ============
__global__ void k_wsplit(const float* __restrict__ W1, const float* __restrict__ W2,
                         const float* __restrict__ W3) {
    int stride = gridDim.x * blockDim.x;
    int tid = blockIdx.x * blockDim.x + threadIdx.x;
    for (int i = tid; i < DIM * HID1; i += stride) {
        int k = i >> 9, n = i & 511;
        float w = W1[i];
        __nv_bfloat16 hi = __float2bfloat16(w);
        g_w1hi[n * DIM + k] = hi;
        g_w1lo[n * DIM + k] = __float2bfloat16(w - __bfloat162float(hi));
    }
    for (int i = tid; i < HID1 * HID2; i += stride) {
        int k = i >> 8, n = i & 255;
        float w = W2[i];
        __nv_bfloat16 hi = __float2bfloat16(w);
        g_w2hi[n * HID1 + k] = hi;
        g_w2lo[n * HID1 + k] = __float2bfloat16(w - __bfloat162float(hi));
    }
    for (int i = tid; i < HID2 * DIM; i += stride) {
        int k = i >> 7, n = i & 127;
        float w = W3[i];
        __nv_bfloat16 hi = __float2bfloat16(w);
        g_w3hi[n * HID2 + k] = hi;
        g_w3lo[n * HID2 + k] = __float2bfloat16(w - __bfloat162float(hi));
    }
}

// ============ mma.sync GEMM: 128x128 CTA tile, bf16 hi/lo 3-term, fp32 accum ============
// A: [M,KTOT] row-major bf16 (hi/lo), B: [Nfull,KTOT] row-major bf16 (hi/lo) = W^T.
// K-chunk 64, 2-stage cp.async pipeline. SMEM rows padded to 144B (conflict-free frags).
// EPI 0: bias+SiLU -> bf16 hi/lo out. EPI 1: bias -> L2 norm -> empty mask -> fp32 out.
#define ROWB 144
#define MATB (128 * ROWB)      // 18432
#define STGB (4 * MATB)        // 73728

template<int KTOT, int EPI>
__global__ __launch_bounds__(256)
void gemm_mma(const __nv_bfloat16* __restrict__ aHi, const __nv_bfloat16* __restrict__ aLo,
              const __nv_bfloat16* __restrict__ bHi, const __nv_bfloat16* __restrict__ bLo,
              const float* __restrict__ bias, int Nfull,
              __nv_bfloat16* __restrict__ outHi, __nv_bfloat16* __restrict__ outLo,
              const int* __restrict__ rowcnt, float* __restrict__ outF) {
    constexpr int NCH = KTOT / 64;
    extern __shared__ char sm[];
    const int tid = threadIdx.x, wid = tid >> 5, lane = tid & 31;
    const int wm = wid & 1, wn = wid >> 1;            // 2 (m) x 4 (n) warps
    const int lq = lane & 3, lr = lane >> 2;
    const int bm = blockIdx.y * 128, bn = blockIdx.x * 128;
    const uint32_t smem0 = smem_to_u32(sm);

    float d[4][4][4];
    #pragma unroll
    for (int mt = 0; mt < 4; mt++)
        #pragma unroll
        for (int nt = 0; nt < 4; nt++)
            #pragma unroll
            for (int q = 0; q < 4; q++) d[mt][nt][q] = 0.f;

    auto load_stage = [&](int s, int ch) {
        int k0 = ch * 64;
        uint32_t sb = smem0 + (uint32_t)s * STGB;
        for (int i = tid; i < 1024; i += 256) {
            int r = i >> 3, c = i & 7;
            uint32_t so = (uint32_t)(r * ROWB + c * 16);
            size_t ga = (size_t)(bm + r) * KTOT + k0 + c * 8;
            size_t gb = (size_t)(bn + r) * KTOT + k0 + c * 8;
            cp_async16(sb + 0 * MATB + so, aHi + ga);
            cp_async16(sb + 1 * MATB + so, aLo + ga);
            cp_async16(sb + 2 * MATB + so, bHi + gb);
            cp_async16(sb + 3 * MATB + so, bLo + gb);
        }
    };

    load_stage(0, 0);
    CP_COMMIT();
    for (int ch = 0; ch < NCH; ch++) {
        if (ch + 1 < NCH) { load_stage((ch + 1) & 1, ch + 1); CP_COMMIT(); CP_WAIT(1); }
        else              { CP_WAIT(0); }
        __syncthreads();
        const char* st  = sm + (size_t)(ch & 1) * STGB;
        const char* pAh = st;
        const char* pAl = st + MATB;
        const char* pBh = st + 2 * MATB;
        const char* pBl = st + 3 * MATB;
        #pragma unroll
        for (int ks = 0; ks < 4; ks++) {
            uint32_t Ah[4][4], Bh[4][2];
            #pragma unroll
            for (int mt = 0; mt < 4; mt++) {
                int r0 = wm * 64 + mt * 16 + lr;
                const uint32_t* w0 = (const uint32_t*)(pAh + r0 * ROWB);
                const uint32_t* w1 = (const uint32_t*)(pAh + (r0 + 8) * ROWB);
                Ah[mt][0] = w0[ks * 8 + lq];
                Ah[mt][1] = w1[ks * 8 + lq];
                Ah[mt][2] = w0[ks * 8 + lq + 4];
                Ah[mt][3] = w1[ks * 8 + lq + 4];
            }
            #pragma unroll
            for (int nt = 0; nt < 4; nt++) {
                int n0 = wn * 32 + nt * 8 + lr;
                const uint32_t* wb = (const uint32_t*)(pBh + n0 * ROWB);
                Bh[nt][0] = wb[ks * 8 + lq];
                Bh[nt][1] = wb[ks * 8 + lq + 4];
            }
            #pragma unroll
            for (int mt = 0; mt < 4; mt++)
                #pragma unroll
                for (int nt = 0; nt < 4; nt++) mma_bf16(d[mt][nt], Ah[mt], Bh[nt]);
            {   // A_hi x B_lo
                uint32_t Bl[4][2];
                #pragma unroll
                for (int nt = 0; nt < 4; nt++) {
                    int n0 = wn * 32 + nt * 8 + lr;
                    const uint32_t* wb = (const uint32_t*)(pBl + n0 * ROWB);
                    Bl[nt][0] = wb[ks * 8 + lq];
                    Bl[nt][1] = wb[ks * 8 + lq + 4];
                }
                #pragma unroll
                for (int mt = 0; mt < 4; mt++)
                    #pragma unroll
                    for (int nt = 0; nt < 4; nt++) mma_bf16(d[mt][nt], Ah[mt], Bl[nt]);
            }
            {   // A_lo x B_hi
                uint32_t Al[4][4];
                #pragma unroll
                for (int mt = 0; mt < 4; mt++) {
                    int r0 = wm * 64 + mt * 16 + lr;
                    const uint32_t* w0 = (const uint32_t*)(pAl + r0 * ROWB);
                    const uint32_t* w1 = (const uint32_t*)(pAl + (r0 + 8) * ROWB);
                    Al[mt][0] = w0[ks * 8 + lq];
                    Al[mt][1] = w1[ks * 8 + lq];
                    Al[mt][2] = w0[ks * 8 + lq + 4];
                    Al[mt][3] = w1[ks * 8 + lq + 4];
                }
                #pragma unroll
                for (int mt = 0; mt < 4; mt++)
                    #pragma unroll
                    for (int nt = 0; nt < 4; nt++) mma_bf16(d[mt][nt], Al[mt], Bh[nt]);
            }
        }
        __syncthreads();
    }

    if (EPI == 0) {
        // bias + SiLU + bf16 hi/lo split-store
        #pragma unroll
        for (int mt = 0; mt < 4; mt++) {
            int row0 = bm + wm * 64 + mt * 16 + lr;
            #pragma unroll
            for (int nt = 0; nt < 4; nt++) {
                int col = bn + wn * 32 + nt * 8 + lq * 2;
                float2 bb = *(const float2*)&bias[col];
                #pragma unroll
                for (int h = 0; h < 2; h++) {
                    int row = row0 + h * 8;
                    float x0 = d[mt][nt][2 * h + 0] + bb.x;
                    float x1 = d[mt][nt][2 * h + 1] + bb.y;
                    float s0 = x0 / (1.f + __expf(-x0));
                    float s1 = x1 / (1.f + __expf(-x1));
                    __nv_bfloat16 h0 = __float2bfloat16(s0), h1 = __float2bfloat16(s1);
                    __nv_bfloat16 l0 = __float2bfloat16(s0 - __bfloat162float(h0));
                    __nv_bfloat16 l1 = __float2bfloat16(s1 - __bfloat162float(h1));
                    __nv_bfloat162 ph = __halves2bfloat162(h0, h1);
                    __nv_bfloat162 pl = __halves2bfloat162(l0, l1);
                    size_t go = ((size_t)row * Nfull + col) >> 1;
                    ((uint32_t*)outHi)[go] = *(uint32_t*)&ph;
                    ((uint32_t*)outLo)[go] = *(uint32_t*)&pl;
                }
            }
        }
    } else {
        // bias + L2 norm + empty mask (Nfull == 128, bn == 0); deterministic reduce
        float* sqp = (float*)sm;   // [4 n-warps][128 rows]
        for (int i = tid; i < 512; i += 256) sqp[i] = 0.f;
        __syncthreads();
        #pragma unroll
        for (int mt = 0; mt < 4; mt++) {
            #pragma unroll
            for (int h = 0; h < 2; h++) {
                float s = 0.f;
                #pragma unroll
                for (int nt = 0; nt < 4; nt++) {
                    int col = wn * 32 + nt * 8 + lq * 2;
                    float2 bb = *(const float2*)&bias[col];
                    float e0 = d[mt][nt][2 * h + 0] + bb.x;
                    float e1 = d[mt][nt][2 * h + 1] + bb.y;
                    s += e0 * e0 + e1 * e1;
                }
                s += __shfl_xor_sync(0xffffffffu, s, 1);
                s += __shfl_xor_sync(0xffffffffu, s, 2);
                if (lq == 0) sqp[wn * 128 + wm * 64 + mt * 16 + lr + h * 8] = s;
            }
        }
        __syncthreads();
        #pragma unroll
        for (int mt = 0; mt < 4; mt++) {
            #pragma unroll
            for (int h = 0; h < 2; h++) {
                int rl = wm * 64 + mt * 16 + lr + h * 8;
                float S = sqp[rl] + sqp[128 + rl] + sqp[256 + rl] + sqp[384 + rl];
                float sc = 0.f;
                if (rowcnt[bm + rl] > 0 && S > 0.f) sc = rsqrtf(S);
                #pragma unroll
                for (int nt = 0; nt < 4; nt++) {
                    int col = wn * 32 + nt * 8 + lq * 2;
                    float2 bb = *(const float2*)&bias[col];
                    float2 v;
                    v.x = (d[mt][nt][2 * h + 0] + bb.x) * sc;
                    v.y = (d[mt][nt][2 * h + 1] + bb.y) * sc;
                    *(float2*)&outF[(size_t)(bm + rl) * 128 + col] = v;
                }
            }
        }
    }
}

// ============================ launch ============================
static constexpr int GEMM_SMEM = 2 * STGB;   // 147456

extern "C" void kernel_launch(void* const* d_in, const int* in_sizes, int n_in,
                              void* d_out, int out_size) {
    const float* ad    = (const float*)d_in[0];
    const void*  user  = d_in[1];
    const void*  ts    = d_in[2];
    const void*  click = d_in[3];
    const float* W1 = (const float*)d_in[4];
    const float* b1 = (const float*)d_in[5];
    const float* W2 = (const float*)d_in[6];
    const float* b2 = (const float*)d_in[7];
    const float* W3 = (const float*)d_in[8];
    const float* b3 = (const float*)d_in[9];
    float* out = (float*)d_out;

    cudaFuncSetAttribute(gemm_mma<128, 0>, cudaFuncAttributeMaxDynamicSharedMemorySize, GEMM_SMEM);
    cudaFuncSetAttribute(gemm_mma<512, 0>, cudaFuncAttributeMaxDynamicSharedMemorySize, GEMM_SMEM);
    cudaFuncSetAttribute(gemm_mma<256, 1>, cudaFuncAttributeMaxDynamicSharedMemorySize, GEMM_SMEM);

    __nv_bfloat16 *a0hi, *a0lo, *a1hi, *a1lo, *a2hi, *a2lo;
    __nv_bfloat16 *w1hi, *w1lo, *w2hi, *w2lo, *w3hi, *w3lo;
    int* rowcnt;
    cudaGetSymbolAddress((void**)&a0hi, g_a0hi); cudaGetSymbolAddress((void**)&a0lo, g_a0lo);
    cudaGetSymbolAddress((void**)&a1hi, g_a1hi); cudaGetSymbolAddress((void**)&a1lo, g_a1lo);
    cudaGetSymbolAddress((void**)&a2hi, g_a2hi); cudaGetSymbolAddress((void**)&a2lo, g_a2lo);
    cudaGetSymbolAddress((void**)&w1hi, g_w1hi); cudaGetSymbolAddress((void**)&w1lo, g_w1lo);
    cudaGetSymbolAddress((void**)&w2hi, g_w2hi); cudaGetSymbolAddress((void**)&w2lo, g_w2lo);
    cudaGetSymbolAddress((void**)&w3hi, g_w3hi); cudaGetSymbolAddress((void**)&w3lo, g_w3lo);
    cudaGetSymbolAddress((void**)&rowcnt, g_rowcnt);

    k_prep<<<1, NUSERS>>>(user, ts, click);
    k_wsplit<<<128, 256>>>(W1, W2, W3);
    k_hist<<<NROWS, DIM>>>(ad, user, ts);

    // L1: a0[8192,128] @ w1t[512,128]^T -> silu -> a1 (hi/lo)
    gemm_mma<128, 0><<<dim3(HID1 / 128, NROWS / 128), 256, GEMM_SMEM>>>(
        a0hi, a0lo, w1hi, w1lo, b1, HID1, a1hi, a1lo, nullptr, nullptr);
    // L2: a1[8192,512] @ w2t[256,512]^T -> silu -> a2 (hi/lo)
    gemm_mma<512, 0><<<dim3(HID2 / 128, NROWS / 128), 256, GEMM_SMEM>>>(
        a1hi, a1lo, w2hi, w2lo, b2, HID2, a2hi, a2lo, nullptr, nullptr);
    // L3: a2[8192,256] @ w3t[128,256]^T -> bias -> L2norm -> mask -> out
    gemm_mma<256, 1><<<dim3(1, NROWS / 128), 256, GEMM_SMEM>>>(
        a2hi, a2lo, w3hi, w3lo, b3, DIM, nullptr, nullptr, rowcnt, out);
}